// round 13
// baseline (speedup 1.0000x reference)
#include <cuda_runtime.h>
#include <cuda_fp16.h>
#include <cstdint>

// ---------------- problem constants ----------------
#define B_ROWS   524288
#define N_TASKS  16384          // 32 rows per warp-task
#define THREADS  256            // 8 warps
#define GRID_CTAS 296           // 2 CTAs/SM

// smem layout (bytes)
#define OFF_BFRAG 0u            // 2048 x uint4 = 32768  (W1 fp16 B-fragments)
#define OFF_B1H   32768u        // 128 x u32 = 512 (b1 f16x2 table [kc][tg][nt])
#define OFF_XS32  33280u        // 8 warps x 9216B raw-f32 x stage (32 rows x 288B)
#define XS_STRIDE 9216u
#define SMEM_BYTES 107008u      // 33280 + 8*9216

static __device__ unsigned int g_task_ctr;

// ---------------- helpers ----------------
__device__ __forceinline__ uint32_t smem_u32(const void* p) {
    uint32_t a;
    asm("{ .reg .u64 t; cvta.to.shared.u64 t, %1; cvt.u32.u64 %0, t; }"
        : "=r"(a) : "l"(p));
    return a;
}
// pack two f32 -> f16x2 {lo, hi}
__device__ __forceinline__ uint32_t pack_h2(float lo, float hi) {
    uint32_t r;
    asm("cvt.rn.f16x2.f32 %0, %1, %2;" : "=r"(r) : "f"(hi), "f"(lo));
    return r;
}
__device__ __forceinline__ uint32_t tanh2u(uint32_t v) {
    uint32_t r;
    asm("tanh.approx.f16x2 %0, %1;" : "=r"(r) : "r"(v));
    return r;
}
__device__ __forceinline__ uint32_t hadd2u(uint32_t a, uint32_t b) {
    uint32_t r;
    asm("add.rn.f16x2 %0, %1, %2;" : "=r"(r) : "r"(a), "r"(b));
    return r;
}
// (tanh(v)+1)/2 = sigmoid(2v)
__device__ __forceinline__ float fast_sigmoid2(float v) {
    float e, r;
    asm("ex2.approx.f32 %0, %1;" : "=f"(e) : "f"(-2.885390081777927f * v));
    asm("rcp.approx.f32 %0, %1;" : "=f"(r) : "f"(1.0f + e));
    return r;
}
// async 16B copy gmem -> smem (L1 bypass)
__device__ __forceinline__ void cp_async16(uint32_t dst, const void* src) {
    asm volatile("cp.async.cg.shared.global [%0], [%1], 16;"
                 :: "r"(dst), "l"(src));
}
#define CP_COMMIT() asm volatile("cp.async.commit_group;" ::: "memory")
#define CP_WAIT0()  asm volatile("cp.async.wait_group 0;" ::: "memory")

// f16-acc accumulate: D,C = 2 x f16x2 (GEMM1 and GEMM2)
__device__ __forceinline__ void mma16816h(uint32_t& d0, uint32_t& d1,
                                          uint32_t a0, uint32_t a1, uint32_t a2, uint32_t a3,
                                          uint32_t b0, uint32_t b1) {
    asm volatile(
        "mma.sync.aligned.m16n8k16.row.col.f16.f16.f16.f16 "
        "{%0,%1}, {%2,%3,%4,%5}, {%6,%7}, {%0,%1};"
        : "+r"(d0), "+r"(d1)
        : "r"(a0), "r"(a1), "r"(a2), "r"(a3), "r"(b0), "r"(b1));
}
// f16-acc init: D = A*B + {cin, cin}
__device__ __forceinline__ void mma16816h_init(uint32_t& d0, uint32_t& d1,
                                               uint32_t a0, uint32_t a1, uint32_t a2, uint32_t a3,
                                               uint32_t b0, uint32_t b1, uint32_t cin) {
    asm volatile(
        "mma.sync.aligned.m16n8k16.row.col.f16.f16.f16.f16 "
        "{%0,%1}, {%2,%3,%4,%5}, {%6,%7}, {%8,%8};"
        : "=r"(d0), "=r"(d1)
        : "r"(a0), "r"(a1), "r"(a2), "r"(a3), "r"(b0), "r"(b1), "r"(cin));
}

// ---------------- kernels ----------------
__global__ void sel_reset_kernel() { g_task_ctr = 0u; }

__global__ void __launch_bounds__(THREADS, 2) sel_main_kernel(
    const float* __restrict__ x,    // [B, 64]
    const float* __restrict__ W1,   // [8,32,64] flat: n*64 + i  (n = kc*32+h)
    const float* __restrict__ b1v,  // [256]
    const float* __restrict__ W2v,  // [256]
    const float* __restrict__ b2v,  // [8]
    float* __restrict__ out)        // [B, 8]
{
    extern __shared__ char smem[];
    uint4*     bfrag = (uint4*)(smem + OFF_BFRAG);
    uint32_t*  b1h   = (uint32_t*)(smem + OFF_B1H);

    const int tid  = threadIdx.x;
    const int lane = tid & 31;
    const int wid  = tid >> 5;
    const int g    = lane >> 2;   // group id (row within 8 / out col owner)
    const int tg   = lane & 3;    // thread in group

    // ---- build W1 B-fragments in smem (once per CTA) ----
    for (int idx = tid; idx < 2048; idx += THREADS) {
        int l = idx & 31;
        int rest = idx >> 5;            // kc*8 + ks*2 + ntp
        int ntp = rest & 1;
        int ks = (rest >> 1) & 3;
        int kc = rest >> 3;
        int lg = l >> 2, ltg = l & 3;
        int k0 = ks * 16 + ltg * 2;
        uint32_t v[4];
        #pragma unroll
        for (int j = 0; j < 2; j++) {
            int n = kc * 32 + (ntp * 2 + j) * 8 + lg;
            const float* wp = W1 + n * 64 + k0;
            float2 p0 = *(const float2*)wp;
            float2 p1 = *(const float2*)(wp + 8);
            v[j * 2 + 0] = pack_h2(p0.x, p0.y);
            v[j * 2 + 1] = pack_h2(p1.x, p1.y);
        }
        bfrag[idx] = make_uint4(v[0], v[1], v[2], v[3]);
    }
    // b1 f16x2 table: b1h[kc*16 + tg*4 + nt] = pack(b1[kc*32+nt*8+2tg], +1)
    for (int idx = tid; idx < 128; idx += THREADS) {
        int kc = idx >> 4, tg2 = (idx >> 2) & 3, nt = idx & 3;
        float2 bb = *(const float2*)(b1v + kc * 32 + nt * 8 + 2 * tg2);
        b1h[idx] = pack_h2(bb.x, bb.y);
    }
    __syncthreads();

    // ---- per-lane persistent constants ----
    uint32_t w2r[4];
    #pragma unroll
    for (int p = 0; p < 2; p++)
        #pragma unroll
        for (int j = 0; j < 2; j++) {
            float2 ww = *(const float2*)(W2v + g * 32 + p * 16 + j * 8 + 2 * tg);
            w2r[p * 2 + j] = pack_h2(ww.x, ww.y);
        }
    const float2 b2p = *(const float2*)(b2v + 2 * tg);
    const uint32_t b2h2 = pack_h2(b2p.x, b2p.y);

    const float* xf = (const float*)(smem + OFF_XS32 + (unsigned)wid * XS_STRIDE);
    const uint32_t xsb = smem_u32(xf);

    const uint4* b1h4 = (const uint4*)b1h;       // [kc*4 + tg] -> nt 0..3

    // ---- prologue: grab first task, prefetch its x ----
    unsigned t;
    if (lane == 0) t = atomicAdd(&g_task_ctr, 1u);
    t = __shfl_sync(0xFFFFFFFFu, t, 0);
    if (t < N_TASKS) {
        const char* src = (const char*)(x + (size_t)t * 2048);
        #pragma unroll
        for (int i = 0; i < 16; i++) {
            int idx = i * 32 + lane;           // 512 x 16B chunks
            int r = idx >> 4, j = idx & 15;
            cp_async16(xsb + (uint32_t)(r * 288 + j * 16), src + (size_t)idx * 16);
        }
        CP_COMMIT();
    }

    // ---- pipelined task loop ----
    while (t < N_TASKS) {
        // grab next task id early
        unsigned tn;
        if (lane == 0) tn = atomicAdd(&g_task_ctr, 1u);
        tn = __shfl_sync(0xFFFFFFFFu, tn, 0);

        // wait for this task's x, extract A fragments (f32 -> f16x2)
        CP_WAIT0();
        __syncwarp();
        uint32_t A[2][4][4];
        #pragma unroll
        for (int rb = 0; rb < 2; rb++)
            #pragma unroll
            for (int ks = 0; ks < 4; ks++) {
                const float* p0 = xf + (rb * 16 + g) * 72 + ks * 16 + 2 * tg;
                float2 v0 = *(const float2*)p0;            // row g,   k..k+1
                float2 v1 = *(const float2*)(p0 + 576);    // row g+8
                float2 v2 = *(const float2*)(p0 + 8);      // row g,   k+8..k+9
                float2 v3 = *(const float2*)(p0 + 584);    // row g+8, k+8
                A[rb][ks][0] = pack_h2(v0.x, v0.y);
                A[rb][ks][1] = pack_h2(v1.x, v1.y);
                A[rb][ks][2] = pack_h2(v2.x, v2.y);
                A[rb][ks][3] = pack_h2(v3.x, v3.y);
            }
        __syncwarp();

        // prefetch next task's x
        if (tn < N_TASKS) {
            const char* src = (const char*)(x + (size_t)tn * 2048);
            #pragma unroll
            for (int i = 0; i < 16; i++) {
                int idx = i * 32 + lane;
                int r = idx >> 4, j = idx & 15;
                cp_async16(xsb + (uint32_t)(r * 288 + j * 16), src + (size_t)idx * 16);
            }
            CP_COMMIT();
        }

        const size_t rowbase = (size_t)t * 32;

        // out accumulators split even/odd kc to halve the serial d chain:
        // de (kc 0,2,4,6; seeded with b2), do_ (kc 1,3,5,7; seeded 0).
        uint32_t de[2][2], do_[2][2];
        de[0][0] = b2h2; de[0][1] = b2h2;
        de[1][0] = b2h2; de[1][1] = b2h2;
        do_[0][0] = 0u; do_[0][1] = 0u;
        do_[1][0] = 0u; do_[1][1] = 0u;

        #pragma unroll
        for (int kc = 0; kc < 8; kc++) {
            uint4 bh = b1h4[kc * 4 + tg];   // b1 f16x2 for nt = 0..3

            // GEMM1 (f16 acc): h = x @ W1_kc^T + b1 (via C init)
            uint32_t c[2][4][2];
            #pragma unroll
            for (int ks = 0; ks < 4; ks++)
                #pragma unroll
                for (int ntp = 0; ntp < 2; ntp++) {
                    uint4 bf = bfrag[((kc * 4 + ks) * 2 + ntp) * 32 + lane];
                    uint32_t bh0 = (ntp == 0) ? bh.x : bh.z;
                    uint32_t bh1 = (ntp == 0) ? bh.y : bh.w;
                    #pragma unroll
                    for (int rb = 0; rb < 2; rb++) {
                        if (ks == 0) {
                            mma16816h_init(c[rb][ntp*2+0][0], c[rb][ntp*2+0][1],
                                           A[rb][0][0], A[rb][0][1], A[rb][0][2], A[rb][0][3],
                                           bf.x, bf.y, bh0);
                            mma16816h_init(c[rb][ntp*2+1][0], c[rb][ntp*2+1][1],
                                           A[rb][0][0], A[rb][0][1], A[rb][0][2], A[rb][0][3],
                                           bf.z, bf.w, bh1);
                        } else {
                            mma16816h(c[rb][ntp*2+0][0], c[rb][ntp*2+0][1],
                                      A[rb][ks][0], A[rb][ks][1], A[rb][ks][2], A[rb][ks][3],
                                      bf.x, bf.y);
                            mma16816h(c[rb][ntp*2+1][0], c[rb][ntp*2+1][1],
                                      A[rb][ks][0], A[rb][ks][1], A[rb][ks][2], A[rb][ks][3],
                                      bf.z, bf.w);
                        }
                    }
                }

            // GEMM2 (f16 acc): D_par[:, kc] += tanh(h) @ W2_kc, where
            // D_par alternates even/odd kc (independent chains).
            uint32_t B0p0 = (g == kc) ? w2r[0] : 0u;
            uint32_t B1p0 = (g == kc) ? w2r[1] : 0u;
            uint32_t B0p1 = (g == kc) ? w2r[2] : 0u;
            uint32_t B1p1 = (g == kc) ? w2r[3] : 0u;
            #pragma unroll
            for (int rb = 0; rb < 2; rb++) {
                uint32_t* dp = (kc & 1) ? do_[rb] : de[rb];
                mma16816h(dp[0], dp[1],
                          tanh2u(c[rb][0][0]), tanh2u(c[rb][0][1]),
                          tanh2u(c[rb][1][0]), tanh2u(c[rb][1][1]),
                          B0p0, B1p0);
                mma16816h(dp[0], dp[1],
                          tanh2u(c[rb][2][0]), tanh2u(c[rb][2][1]),
                          tanh2u(c[rb][3][0]), tanh2u(c[rb][3][1]),
                          B0p1, B1p1);
            }
        }

        // final: merge halves, out = sigmoid(2*D); coalesced float2 stores
        #pragma unroll
        for (int rb = 0; rb < 2; rb++) {
            uint32_t m0 = hadd2u(de[rb][0], do_[rb][0]);
            uint32_t m1 = hadd2u(de[rb][1], do_[rb][1]);
            __half2 h0 = *reinterpret_cast<__half2*>(&m0);
            __half2 h1 = *reinterpret_cast<__half2*>(&m1);
            float* orow = out + (rowbase + (unsigned)(rb * 16 + g)) * 8 + 2 * tg;
            *(float2*)orow = make_float2(fast_sigmoid2(__low2float(h0)),
                                         fast_sigmoid2(__high2float(h0)));
            *(float2*)(orow + 64) = make_float2(fast_sigmoid2(__low2float(h1)),
                                                fast_sigmoid2(__high2float(h1)));
        }

        t = tn;
    }
}

// ---------------- launch ----------------
extern "C" void kernel_launch(void* const* d_in, const int* in_sizes, int n_in,
                              void* d_out, int out_size) {
    const float* x  = (const float*)d_in[0];
    const float* W1 = (const float*)d_in[1];
    const float* b1 = (const float*)d_in[2];
    const float* W2 = (const float*)d_in[3];
    const float* b2 = (const float*)d_in[4];
    float* out = (float*)d_out;

    cudaFuncSetAttribute(sel_main_kernel,
                         cudaFuncAttributeMaxDynamicSharedMemorySize, SMEM_BYTES);

    sel_reset_kernel<<<1, 1>>>();
    sel_main_kernel<<<GRID_CTAS, THREADS, SMEM_BYTES>>>(x, W1, b1, W2, b2, out);
}

// round 14
// speedup vs baseline: 1.4654x; 1.4654x over previous
#include <cuda_runtime.h>
#include <cuda_fp16.h>
#include <cstdint>

// ---------------- problem constants ----------------
#define B_ROWS   524288
#define N_TASKS  16384          // 32 rows per warp-task
#define THREADS  256            // 8 warps
#define GRID_CTAS 296           // 2 CTAs/SM

// smem layout (bytes)
#define OFF_BFRAG 0u            // 2048 x uint4 = 32768  (W1 fp16 B-fragments)
#define OFF_B1H   32768u        // 128 x u32 = 512 (b1 f16x2 table [kc][tg][nt])
#define OFF_XS32  33280u        // 8 warps x 9216B raw-f32 x stage (32 rows x 288B)
#define XS_STRIDE 9216u
#define SMEM_BYTES 107008u      // 33280 + 8*9216

static __device__ unsigned int g_task_ctr;

// ---------------- helpers ----------------
__device__ __forceinline__ uint32_t smem_u32(const void* p) {
    uint32_t a;
    asm("{ .reg .u64 t; cvta.to.shared.u64 t, %1; cvt.u32.u64 %0, t; }"
        : "=r"(a) : "l"(p));
    return a;
}
// pack two f32 -> f16x2 {lo, hi}
__device__ __forceinline__ uint32_t pack_h2(float lo, float hi) {
    uint32_t r;
    asm("cvt.rn.f16x2.f32 %0, %1, %2;" : "=r"(r) : "f"(hi), "f"(lo));
    return r;
}
__device__ __forceinline__ uint32_t tanh2u(uint32_t v) {
    uint32_t r;
    asm("tanh.approx.f16x2 %0, %1;" : "=r"(r) : "r"(v));
    return r;
}
__device__ __forceinline__ uint32_t hadd2u(uint32_t a, uint32_t b) {
    uint32_t r;
    asm("add.rn.f16x2 %0, %1, %2;" : "=r"(r) : "r"(a), "r"(b));
    return r;
}
// (tanh(v)+1)/2 = sigmoid(2v)
__device__ __forceinline__ float fast_sigmoid2(float v) {
    float e, r;
    asm("ex2.approx.f32 %0, %1;" : "=f"(e) : "f"(-2.885390081777927f * v));
    asm("rcp.approx.f32 %0, %1;" : "=f"(r) : "f"(1.0f + e));
    return r;
}
// async 16B copy gmem -> smem (L1 bypass)
__device__ __forceinline__ void cp_async16(uint32_t dst, const void* src) {
    asm volatile("cp.async.cg.shared.global [%0], [%1], 16;"
                 :: "r"(dst), "l"(src));
}
#define CP_COMMIT() asm volatile("cp.async.commit_group;" ::: "memory")
#define CP_WAIT0()  asm volatile("cp.async.wait_group 0;" ::: "memory")

// f16-acc accumulate: D,C = 2 x f16x2 (GEMM1 and GEMM2)
__device__ __forceinline__ void mma16816h(uint32_t& d0, uint32_t& d1,
                                          uint32_t a0, uint32_t a1, uint32_t a2, uint32_t a3,
                                          uint32_t b0, uint32_t b1) {
    asm volatile(
        "mma.sync.aligned.m16n8k16.row.col.f16.f16.f16.f16 "
        "{%0,%1}, {%2,%3,%4,%5}, {%6,%7}, {%0,%1};"
        : "+r"(d0), "+r"(d1)
        : "r"(a0), "r"(a1), "r"(a2), "r"(a3), "r"(b0), "r"(b1));
}
// f16-acc init: D = A*B + {cin, cin}
__device__ __forceinline__ void mma16816h_init(uint32_t& d0, uint32_t& d1,
                                               uint32_t a0, uint32_t a1, uint32_t a2, uint32_t a3,
                                               uint32_t b0, uint32_t b1, uint32_t cin) {
    asm volatile(
        "mma.sync.aligned.m16n8k16.row.col.f16.f16.f16.f16 "
        "{%0,%1}, {%2,%3,%4,%5}, {%6,%7}, {%8,%8};"
        : "=r"(d0), "=r"(d1)
        : "r"(a0), "r"(a1), "r"(a2), "r"(a3), "r"(b0), "r"(b1), "r"(cin));
}

// ---------------- kernels ----------------
__global__ void sel_reset_kernel() { g_task_ctr = 0u; }

__global__ void __launch_bounds__(THREADS, 2) sel_main_kernel(
    const float* __restrict__ x,    // [B, 64]
    const float* __restrict__ W1,   // [8,32,64] flat: n*64 + i  (n = kc*32+h)
    const float* __restrict__ b1v,  // [256]
    const float* __restrict__ W2v,  // [256]
    const float* __restrict__ b2v,  // [8]
    float* __restrict__ out)        // [B, 8]
{
    extern __shared__ char smem[];
    uint4*     bfrag = (uint4*)(smem + OFF_BFRAG);
    uint32_t*  b1h   = (uint32_t*)(smem + OFF_B1H);

    const int tid  = threadIdx.x;
    const int lane = tid & 31;
    const int wid  = tid >> 5;
    const int g    = lane >> 2;   // group id (row within 8 / out col owner)
    const int tg   = lane & 3;    // thread in group

    // ---- build W1 B-fragments in smem (once per CTA) ----
    for (int idx = tid; idx < 2048; idx += THREADS) {
        int l = idx & 31;
        int rest = idx >> 5;            // kc*8 + ks*2 + ntp
        int ntp = rest & 1;
        int ks = (rest >> 1) & 3;
        int kc = rest >> 3;
        int lg = l >> 2, ltg = l & 3;
        int k0 = ks * 16 + ltg * 2;
        uint32_t v[4];
        #pragma unroll
        for (int j = 0; j < 2; j++) {
            int n = kc * 32 + (ntp * 2 + j) * 8 + lg;
            const float* wp = W1 + n * 64 + k0;
            float2 p0 = *(const float2*)wp;
            float2 p1 = *(const float2*)(wp + 8);
            v[j * 2 + 0] = pack_h2(p0.x, p0.y);
            v[j * 2 + 1] = pack_h2(p1.x, p1.y);
        }
        bfrag[idx] = make_uint4(v[0], v[1], v[2], v[3]);
    }
    // b1 f16x2 table: b1h[kc*16 + tg*4 + nt] = pack(b1[kc*32+nt*8+2tg], +1)
    for (int idx = tid; idx < 128; idx += THREADS) {
        int kc = idx >> 4, tg2 = (idx >> 2) & 3, nt = idx & 3;
        float2 bb = *(const float2*)(b1v + kc * 32 + nt * 8 + 2 * tg2);
        b1h[idx] = pack_h2(bb.x, bb.y);
    }
    __syncthreads();

    // ---- per-lane persistent constants ----
    uint32_t w2r[4];
    #pragma unroll
    for (int p = 0; p < 2; p++)
        #pragma unroll
        for (int j = 0; j < 2; j++) {
            float2 ww = *(const float2*)(W2v + g * 32 + p * 16 + j * 8 + 2 * tg);
            w2r[p * 2 + j] = pack_h2(ww.x, ww.y);
        }
    const float2 b2p = *(const float2*)(b2v + 2 * tg);
    const uint32_t b2h2 = pack_h2(b2p.x, b2p.y);

    const float* xf = (const float*)(smem + OFF_XS32 + (unsigned)wid * XS_STRIDE);
    const uint32_t xsb = smem_u32(xf);

    const uint4* b1h4 = (const uint4*)b1h;       // [kc*4 + tg] -> nt 0..3

    // ---- prologue: grab first task, prefetch its x ----
    unsigned t;
    if (lane == 0) t = atomicAdd(&g_task_ctr, 1u);
    t = __shfl_sync(0xFFFFFFFFu, t, 0);
    if (t < N_TASKS) {
        const char* src = (const char*)(x + (size_t)t * 2048);
        #pragma unroll
        for (int i = 0; i < 16; i++) {
            int idx = i * 32 + lane;           // 512 x 16B chunks
            int r = idx >> 4, j = idx & 15;
            cp_async16(xsb + (uint32_t)(r * 288 + j * 16), src + (size_t)idx * 16);
        }
        CP_COMMIT();
    }

    // ---- pipelined task loop ----
    while (t < N_TASKS) {
        // grab next task id early
        unsigned tn;
        if (lane == 0) tn = atomicAdd(&g_task_ctr, 1u);
        tn = __shfl_sync(0xFFFFFFFFu, tn, 0);

        // wait for this task's x, extract A fragments (f32 -> f16x2)
        CP_WAIT0();
        __syncwarp();
        uint32_t A[2][4][4];
        #pragma unroll
        for (int rb = 0; rb < 2; rb++)
            #pragma unroll
            for (int ks = 0; ks < 4; ks++) {
                const float* p0 = xf + (rb * 16 + g) * 72 + ks * 16 + 2 * tg;
                float2 v0 = *(const float2*)p0;            // row g,   k..k+1
                float2 v1 = *(const float2*)(p0 + 576);    // row g+8
                float2 v2 = *(const float2*)(p0 + 8);      // row g,   k+8..k+9
                float2 v3 = *(const float2*)(p0 + 584);    // row g+8, k+8
                A[rb][ks][0] = pack_h2(v0.x, v0.y);
                A[rb][ks][1] = pack_h2(v1.x, v1.y);
                A[rb][ks][2] = pack_h2(v2.x, v2.y);
                A[rb][ks][3] = pack_h2(v3.x, v3.y);
            }
        __syncwarp();

        // prefetch next task's x
        if (tn < N_TASKS) {
            const char* src = (const char*)(x + (size_t)tn * 2048);
            #pragma unroll
            for (int i = 0; i < 16; i++) {
                int idx = i * 32 + lane;
                int r = idx >> 4, j = idx & 15;
                cp_async16(xsb + (uint32_t)(r * 288 + j * 16), src + (size_t)idx * 16);
            }
            CP_COMMIT();
        }

        const size_t rowbase = (size_t)t * 32;

        // out accumulators split even/odd kc (halved serial chain).
        // Plain scalar registers only — no runtime-indexed arrays.
        uint32_t de00 = b2h2, de01 = b2h2, de10 = b2h2, de11 = b2h2;  // kc even
        uint32_t do00 = 0u,   do01 = 0u,   do10 = 0u,   do11 = 0u;    // kc odd

        #pragma unroll
        for (int kc = 0; kc < 8; kc++) {
            uint4 bh = b1h4[kc * 4 + tg];   // b1 f16x2 for nt = 0..3

            // GEMM1 (f16 acc): h = x @ W1_kc^T + b1 (via C init)
            uint32_t c[2][4][2];
            #pragma unroll
            for (int ks = 0; ks < 4; ks++)
                #pragma unroll
                for (int ntp = 0; ntp < 2; ntp++) {
                    uint4 bf = bfrag[((kc * 4 + ks) * 2 + ntp) * 32 + lane];
                    uint32_t bh0 = (ntp == 0) ? bh.x : bh.z;
                    uint32_t bh1 = (ntp == 0) ? bh.y : bh.w;
                    #pragma unroll
                    for (int rb = 0; rb < 2; rb++) {
                        if (ks == 0) {
                            mma16816h_init(c[rb][ntp*2+0][0], c[rb][ntp*2+0][1],
                                           A[rb][0][0], A[rb][0][1], A[rb][0][2], A[rb][0][3],
                                           bf.x, bf.y, bh0);
                            mma16816h_init(c[rb][ntp*2+1][0], c[rb][ntp*2+1][1],
                                           A[rb][0][0], A[rb][0][1], A[rb][0][2], A[rb][0][3],
                                           bf.z, bf.w, bh1);
                        } else {
                            mma16816h(c[rb][ntp*2+0][0], c[rb][ntp*2+0][1],
                                      A[rb][ks][0], A[rb][ks][1], A[rb][ks][2], A[rb][ks][3],
                                      bf.x, bf.y);
                            mma16816h(c[rb][ntp*2+1][0], c[rb][ntp*2+1][1],
                                      A[rb][ks][0], A[rb][ks][1], A[rb][ks][2], A[rb][ks][3],
                                      bf.z, bf.w);
                        }
                    }
                }

            // GEMM2 (f16 acc): even kc -> de*, odd kc -> do* (independent
            // chains; compile-time branch in fully unrolled loop).
            uint32_t B0p0 = (g == kc) ? w2r[0] : 0u;
            uint32_t B1p0 = (g == kc) ? w2r[1] : 0u;
            uint32_t B0p1 = (g == kc) ? w2r[2] : 0u;
            uint32_t B1p1 = (g == kc) ? w2r[3] : 0u;
            if ((kc & 1) == 0) {
                mma16816h(de00, de01,
                          tanh2u(c[0][0][0]), tanh2u(c[0][0][1]),
                          tanh2u(c[0][1][0]), tanh2u(c[0][1][1]), B0p0, B1p0);
                mma16816h(de00, de01,
                          tanh2u(c[0][2][0]), tanh2u(c[0][2][1]),
                          tanh2u(c[0][3][0]), tanh2u(c[0][3][1]), B0p1, B1p1);
                mma16816h(de10, de11,
                          tanh2u(c[1][0][0]), tanh2u(c[1][0][1]),
                          tanh2u(c[1][1][0]), tanh2u(c[1][1][1]), B0p0, B1p0);
                mma16816h(de10, de11,
                          tanh2u(c[1][2][0]), tanh2u(c[1][2][1]),
                          tanh2u(c[1][3][0]), tanh2u(c[1][3][1]), B0p1, B1p1);
            } else {
                mma16816h(do00, do01,
                          tanh2u(c[0][0][0]), tanh2u(c[0][0][1]),
                          tanh2u(c[0][1][0]), tanh2u(c[0][1][1]), B0p0, B1p0);
                mma16816h(do00, do01,
                          tanh2u(c[0][2][0]), tanh2u(c[0][2][1]),
                          tanh2u(c[0][3][0]), tanh2u(c[0][3][1]), B0p1, B1p1);
                mma16816h(do10, do11,
                          tanh2u(c[1][0][0]), tanh2u(c[1][0][1]),
                          tanh2u(c[1][1][0]), tanh2u(c[1][1][1]), B0p0, B1p0);
                mma16816h(do10, do11,
                          tanh2u(c[1][2][0]), tanh2u(c[1][2][1]),
                          tanh2u(c[1][3][0]), tanh2u(c[1][3][1]), B0p1, B1p1);
            }
        }

        // final: merge halves, out = sigmoid(2*D); coalesced float2 stores
        {
            uint32_t m0 = hadd2u(de00, do00);
            uint32_t m1 = hadd2u(de01, do01);
            __half2 h0 = *reinterpret_cast<__half2*>(&m0);
            __half2 h1 = *reinterpret_cast<__half2*>(&m1);
            float* orow = out + (rowbase + (unsigned)g) * 8 + 2 * tg;
            *(float2*)orow = make_float2(fast_sigmoid2(__low2float(h0)),
                                         fast_sigmoid2(__high2float(h0)));
            *(float2*)(orow + 64) = make_float2(fast_sigmoid2(__low2float(h1)),
                                                fast_sigmoid2(__high2float(h1)));
        }
        {
            uint32_t m0 = hadd2u(de10, do10);
            uint32_t m1 = hadd2u(de11, do11);
            __half2 h0 = *reinterpret_cast<__half2*>(&m0);
            __half2 h1 = *reinterpret_cast<__half2*>(&m1);
            float* orow = out + (rowbase + (unsigned)(16 + g)) * 8 + 2 * tg;
            *(float2*)orow = make_float2(fast_sigmoid2(__low2float(h0)),
                                         fast_sigmoid2(__high2float(h0)));
            *(float2*)(orow + 64) = make_float2(fast_sigmoid2(__low2float(h1)),
                                                fast_sigmoid2(__high2float(h1)));
        }

        t = tn;
    }
}

// ---------------- launch ----------------
extern "C" void kernel_launch(void* const* d_in, const int* in_sizes, int n_in,
                              void* d_out, int out_size) {
    const float* x  = (const float*)d_in[0];
    const float* W1 = (const float*)d_in[1];
    const float* b1 = (const float*)d_in[2];
    const float* W2 = (const float*)d_in[3];
    const float* b2 = (const float*)d_in[4];
    float* out = (float*)d_out;

    cudaFuncSetAttribute(sel_main_kernel,
                         cudaFuncAttributeMaxDynamicSharedMemorySize, SMEM_BYTES);

    sel_reset_kernel<<<1, 1>>>();
    sel_main_kernel<<<GRID_CTAS, THREADS, SMEM_BYTES>>>(x, W1, b1, W2, b2, out);
}